// round 1
// baseline (speedup 1.0000x reference)
#include <cuda_runtime.h>
#include <math.h>

// Problem constants
#define B_ 2
#define T_ 2048
#define C_ 1024
#define H_ 16
#define D_ 64
#define M_ (B_*T_)   // 4096 rows for the projection GEMMs

// log2(10000)/32  (for inv_freq = 10000^(-j/32) = 2^(-j * L32))
#define L32 0.4152410118609203f

// Scratch (device globals: allocation-free per harness rules)
__device__ float g_Q[B_*H_*T_*D_];   // [b][h][t][d]
__device__ float g_K[B_*H_*T_*D_];
__device__ float g_V[B_*H_*T_*D_];
__device__ float g_A[B_*T_*C_];      // attention context, [b][t][h*64+d]

// ---------------------------------------------------------------------------
// 64x64 GEMM core:  acc(4x4 per thread) = X[m0:m0+64, :] @ W[n0:n0+64, :]^T
// X, W row-major with K=1024 contiguous. Smem tiles stored k-major so the
// inner loop is 2x LDS.128 + 16 FFMA.
// ---------------------------------------------------------------------------
__device__ __forceinline__ void gemm64x64(const float* __restrict__ X,
                                          const float* __restrict__ W,
                                          int m0, int n0,
                                          float (*As)[68], float (*Bs)[68],
                                          float acc[4][4])
{
    const int tid = threadIdx.x;
    const int tx  = tid & 15;       // n sub-tile
    const int ty  = tid >> 4;       // m sub-tile
    const int lr  = tid >> 2;       // 0..63 : row for cooperative loads
    const int lc4 = (tid & 3) << 2; // 0,4,8,12 : k-offset (float4)

    #pragma unroll
    for (int i = 0; i < 4; i++)
        #pragma unroll
        for (int j = 0; j < 4; j++) acc[i][j] = 0.f;

    for (int k0 = 0; k0 < C_; k0 += 16) {
        float4 av = *(const float4*)&X[(size_t)(m0 + lr) * C_ + k0 + lc4];
        float4 bv = *(const float4*)&W[(size_t)(n0 + lr) * C_ + k0 + lc4];
        __syncthreads();   // previous iteration's reads done before overwrite
        As[lc4 + 0][lr] = av.x; As[lc4 + 1][lr] = av.y;
        As[lc4 + 2][lr] = av.z; As[lc4 + 3][lr] = av.w;
        Bs[lc4 + 0][lr] = bv.x; Bs[lc4 + 1][lr] = bv.y;
        Bs[lc4 + 2][lr] = bv.z; Bs[lc4 + 3][lr] = bv.w;
        __syncthreads();
        #pragma unroll
        for (int kk = 0; kk < 16; kk++) {
            float4 a4 = *(const float4*)&As[kk][4 * ty];
            float4 b4 = *(const float4*)&Bs[kk][4 * tx];
            float a[4] = {a4.x, a4.y, a4.z, a4.w};
            float b[4] = {b4.x, b4.y, b4.z, b4.w};
            #pragma unroll
            for (int i = 0; i < 4; i++)
                #pragma unroll
                for (int j = 0; j < 4; j++)
                    acc[i][j] += a[i] * b[j];
        }
    }
}

__device__ __forceinline__ float inv_freq_f(int j) {
    // 10000^(-j/32)
    return exp2f(-(float)j * L32);
}

// ---------------------------------------------------------------------------
// QKV projection (+bias, +RoPE for q,k). blockIdx.z: 0=q 1=k 2=v.
// Writes [b][h][t][d] layout.
// RoPE (matches reference exactly):
//   out[2i]   = y[2i]  *cos(t*f[(2i)&31])   - y[2i+1]*sin(t*f[(2i)&31])
//   out[2i+1] = y[2i+1]*cos(t*f[(2i+1)&31]) + y[2i]  *sin(t*f[(2i+1)&31])
// ---------------------------------------------------------------------------
__global__ __launch_bounds__(256)
void qkv_kernel(const float* __restrict__ x,
                const float* __restrict__ wq, const float* __restrict__ bq,
                const float* __restrict__ wk, const float* __restrict__ bk,
                const float* __restrict__ wv, const float* __restrict__ bv)
{
    __shared__ float As[16][68], Bs[16][68];
    const int z = blockIdx.z;
    const float* W    = (z == 0) ? wq : (z == 1) ? wk : wv;
    const float* bias = (z == 0) ? bq : (z == 1) ? bk : bv;
    float* dst        = (z == 0) ? g_Q : (z == 1) ? g_K : g_V;
    const bool rope   = (z < 2);

    const int m0 = blockIdx.y * 64;
    const int n0 = blockIdx.x * 64;

    float acc[4][4];
    gemm64x64(x, W, m0, n0, As, Bs, acc);

    const int tx = threadIdx.x & 15, ty = threadIdx.x >> 4;
    const int nbase = n0 + 4 * tx;           // multiple of 4 -> even-aligned pairs

    #pragma unroll
    for (int i = 0; i < 4; i++) {
        const int m = m0 + 4 * ty + i;
        const int b = m >> 11;               // / 2048
        const int t = m & 2047;
        float v[4];
        #pragma unroll
        for (int j = 0; j < 4; j++)
            v[j] = acc[i][j] + bias[nbase + j];

        if (rope) {
            const float tf = (float)t;
            #pragma unroll
            for (int p = 0; p < 2; p++) {
                const int de = (nbase + 2 * p) & 63;     // even head-dim index
                const float fe = inv_freq_f(de & 31);
                const float fo = inv_freq_f((de + 1) & 31);
                const float ae = tf * fe, ao = tf * fo;
                const float ce = cosf(ae), se = sinf(ae);
                const float co = cosf(ao), so = sinf(ao);
                const float e = v[2 * p], o = v[2 * p + 1];
                v[2 * p]     = e * ce - o * se;
                v[2 * p + 1] = o * co + e * so;
            }
        }
        #pragma unroll
        for (int j = 0; j < 4; j++) {
            const int n = nbase + j;
            const int h = n >> 6, d = n & 63;
            dst[(size_t)((b * H_ + h) * T_ + t) * D_ + d] = v[j];
        }
    }
}

// ---------------------------------------------------------------------------
// Flash attention: per CTA = (q-tile of 64, one (b,h)). 128 threads.
// KV tile = 32. Online softmax with running max/sum. fp32 throughout.
// Writes context to g_A in [b][t][h*64+d] layout (ready for output GEMM).
// ---------------------------------------------------------------------------
__global__ __launch_bounds__(128)
void attn_kernel()
{
    __shared__ float Qt[64][68];   // [d][q], pre-scaled by 1/8
    __shared__ float Kt[64][36];   // [d][kv]
    __shared__ float Vs[32][68];   // [kv][d]
    __shared__ float Pt[32][68];   // [kv][q]   (scores -> probabilities)
    __shared__ float m_s[64], l_s[64], alpha_s[64];
    __shared__ float pbuf[2][64];

    const int tid = threadIdx.x;
    const int bh  = blockIdx.y;           // b*16 + h
    const int q0  = blockIdx.x * 64;
    const float* Qg = g_Q + (size_t)bh * T_ * D_;
    const float* Kg = g_K + (size_t)bh * T_ * D_;
    const float* Vg = g_V + (size_t)bh * T_ * D_;

    const int tk = tid & 7;               // 0..7
    const int tq = tid >> 3;              // 0..15

    // Load Q tile transposed, scaled by 1/sqrt(D)=0.125
    #pragma unroll
    for (int e = tid; e < 64 * 16; e += 128) {        // e indexes float4s
        const int row = e >> 4, c4 = (e & 15) << 2;
        float4 v = *(const float4*)&Qg[(size_t)(q0 + row) * D_ + c4];
        Qt[c4 + 0][row] = v.x * 0.125f;
        Qt[c4 + 1][row] = v.y * 0.125f;
        Qt[c4 + 2][row] = v.z * 0.125f;
        Qt[c4 + 3][row] = v.w * 0.125f;
    }
    if (tid < 64) { m_s[tid] = -INFINITY; l_s[tid] = 0.f; }

    float O[4][8];
    #pragma unroll
    for (int i = 0; i < 4; i++)
        #pragma unroll
        for (int j = 0; j < 8; j++) O[i][j] = 0.f;
    __syncthreads();

    for (int kv0 = 0; kv0 < T_; kv0 += 32) {
        // Load K (transposed) and V (row-major) tiles
        #pragma unroll
        for (int e = tid; e < 32 * 16; e += 128) {
            const int row = e >> 4, c4 = (e & 15) << 2;
            float4 kvv = *(const float4*)&Kg[(size_t)(kv0 + row) * D_ + c4];
            Kt[c4 + 0][row] = kvv.x; Kt[c4 + 1][row] = kvv.y;
            Kt[c4 + 2][row] = kvv.z; Kt[c4 + 3][row] = kvv.w;
            float4 vv = *(const float4*)&Vg[(size_t)(kv0 + row) * D_ + c4];
            *(float4*)&Vs[row][c4] = vv;
        }
        __syncthreads();

        // S = (Q/8) @ K^T  : thread computes rows 4tq..+3, cols 4tk..+3
        float s[4][4];
        #pragma unroll
        for (int i = 0; i < 4; i++)
            #pragma unroll
            for (int j = 0; j < 4; j++) s[i][j] = 0.f;
        #pragma unroll 8
        for (int d = 0; d < 64; d++) {
            float4 a4 = *(const float4*)&Qt[d][4 * tq];
            float4 b4 = *(const float4*)&Kt[d][4 * tk];
            float a[4] = {a4.x, a4.y, a4.z, a4.w};
            float b[4] = {b4.x, b4.y, b4.z, b4.w};
            #pragma unroll
            for (int i = 0; i < 4; i++)
                #pragma unroll
                for (int j = 0; j < 4; j++)
                    s[i][j] += a[i] * b[j];
        }
        #pragma unroll
        for (int i = 0; i < 4; i++)
            #pragma unroll
            for (int j = 0; j < 4; j++)
                Pt[4 * tk + j][4 * tq + i] = s[i][j];
        __syncthreads();

        // Online softmax. Row r handled by threads (r, r+64): each scans 16.
        const int r  = tid & 63;
        const int hh = tid >> 6;        // 0/1
        float mx = -INFINITY;
        #pragma unroll
        for (int j = 0; j < 16; j++)
            mx = fmaxf(mx, Pt[hh * 16 + j][r]);
        pbuf[hh][r] = mx;
        __syncthreads();
        if (tid < 64) {
            const float nm = fmaxf(m_s[tid], fmaxf(pbuf[0][tid], pbuf[1][tid]));
            alpha_s[tid] = expf(m_s[tid] - nm);
            m_s[tid] = nm;
        }
        __syncthreads();
        {
            const float mrow = m_s[r];
            float ssum = 0.f;
            #pragma unroll
            for (int j = 0; j < 16; j++) {
                const int kv = hh * 16 + j;
                const float e = expf(Pt[kv][r] - mrow);
                Pt[kv][r] = e;
                ssum += e;
            }
            pbuf[hh][r] = ssum;
        }
        __syncthreads();
        if (tid < 64)
            l_s[tid] = l_s[tid] * alpha_s[tid] + pbuf[0][tid] + pbuf[1][tid];
        __syncthreads();

        // Rescale O and accumulate P @ V. Thread: rows 4tq..+3, dims 8tk..+7.
        float al[4];
        #pragma unroll
        for (int i = 0; i < 4; i++) al[i] = alpha_s[4 * tq + i];
        #pragma unroll
        for (int i = 0; i < 4; i++)
            #pragma unroll
            for (int j = 0; j < 8; j++) O[i][j] *= al[i];

        #pragma unroll 4
        for (int kv = 0; kv < 32; kv++) {
            float4 p4 = *(const float4*)&Pt[kv][4 * tq];
            float4 v0 = *(const float4*)&Vs[kv][8 * tk];
            float4 v1 = *(const float4*)&Vs[kv][8 * tk + 4];
            float p[4] = {p4.x, p4.y, p4.z, p4.w};
            float vv[8] = {v0.x, v0.y, v0.z, v0.w, v1.x, v1.y, v1.z, v1.w};
            #pragma unroll
            for (int i = 0; i < 4; i++)
                #pragma unroll
                for (int j = 0; j < 8; j++)
                    O[i][j] += p[i] * vv[j];
        }
        __syncthreads();   // protect Kt/Vs/Pt before next tile
    }

    // Finalize: divide by l, write to g_A[b][t][h*64+d]
    const int b = bh >> 4, h = bh & 15;
    #pragma unroll
    for (int i = 0; i < 4; i++) {
        const float linv = 1.f / l_s[4 * tq + i];
        const int t = q0 + 4 * tq + i;
        float* dst = &g_A[(size_t)(b * T_ + t) * C_ + h * D_ + 8 * tk];
        float4 o0 = make_float4(O[i][0] * linv, O[i][1] * linv,
                                O[i][2] * linv, O[i][3] * linv);
        float4 o1 = make_float4(O[i][4] * linv, O[i][5] * linv,
                                O[i][6] * linv, O[i][7] * linv);
        *(float4*)&dst[0] = o0;
        *(float4*)&dst[4] = o1;
    }
}

// ---------------------------------------------------------------------------
// Output projection: out = A @ wo^T + bo
// ---------------------------------------------------------------------------
__global__ __launch_bounds__(256)
void oproj_kernel(const float* __restrict__ wo, const float* __restrict__ bo,
                  float* __restrict__ out)
{
    __shared__ float As[16][68], Bs[16][68];
    const int m0 = blockIdx.y * 64;
    const int n0 = blockIdx.x * 64;

    float acc[4][4];
    gemm64x64(g_A, wo, m0, n0, As, Bs, acc);

    const int tx = threadIdx.x & 15, ty = threadIdx.x >> 4;
    const int nbase = n0 + 4 * tx;
    float4 bb = *(const float4*)&bo[nbase];
    #pragma unroll
    for (int i = 0; i < 4; i++) {
        const int m = m0 + 4 * ty + i;
        float4 o = make_float4(acc[i][0] + bb.x, acc[i][1] + bb.y,
                               acc[i][2] + bb.z, acc[i][3] + bb.w);
        *(float4*)&out[(size_t)m * C_ + nbase] = o;
    }
}

// ---------------------------------------------------------------------------
extern "C" void kernel_launch(void* const* d_in, const int* in_sizes, int n_in,
                              void* d_out, int out_size)
{
    const float* x  = (const float*)d_in[0];
    const float* wq = (const float*)d_in[1];
    const float* bq = (const float*)d_in[2];
    const float* wk = (const float*)d_in[3];
    const float* bk = (const float*)d_in[4];
    const float* wv = (const float*)d_in[5];
    const float* bv = (const float*)d_in[6];
    const float* wo = (const float*)d_in[7];
    const float* bo = (const float*)d_in[8];
    float* out = (float*)d_out;

    dim3 gqkv(C_ / 64, M_ / 64, 3);         // (16, 64, 3)
    qkv_kernel<<<gqkv, 256>>>(x, wq, bq, wk, bk, wv, bv);

    dim3 gattn(T_ / 64, B_ * H_);           // (32, 32)
    attn_kernel<<<gattn, 128>>>();

    dim3 gout(C_ / 64, M_ / 64);            // (16, 64)
    oproj_kernel<<<gout, 256>>>(wo, bo, out);
}

// round 5
// speedup vs baseline: 1.3511x; 1.3511x over previous
#include <cuda_runtime.h>
#include <cuda_bf16.h>
#include <math.h>
#include <stdint.h>

// Problem constants
#define B_ 2
#define T_ 2048
#define C_ 1024
#define H_ 16
#define D_ 64
#define M_ (B_*T_)

// log2(10000)/32
#define L32 0.4152410118609203f

// Scratch (device globals: allocation-free per harness rules)
__device__ float g_Q[B_*H_*T_*D_];   // [b][h][t][d]
__device__ float g_K[B_*H_*T_*D_];
__device__ float g_V[B_*H_*T_*D_];
__device__ float g_A[B_*T_*C_];      // attention context, [b][t][h*64+d]
__device__ float g_cos[T_*D_];
__device__ float g_sin[T_*D_];

// bf16 hi/lo split copies (for 3-term compensated HMMA GEMMs)
__device__ __nv_bfloat16 g_xhi[M_*C_], g_xlo[M_*C_];
__device__ __nv_bfloat16 g_wHi[3][C_*C_], g_wLo[3][C_*C_];
__device__ __nv_bfloat16 g_woHi[C_*C_], g_woLo[C_*C_];
__device__ __nv_bfloat16 g_aHi[M_*C_], g_aLo[M_*C_];

// Smem tile: 128 rows x 32 bf16; row padded 64B->80B (ldmatrix conflict-free)
#define TILEB (128*80)   // 10240 bytes

__device__ __forceinline__ uint32_t smem_u32(const void* p) {
    uint32_t a;
    asm("{ .reg .u64 t; cvta.to.shared.u64 t, %1; cvt.u32.u64 %0, t; }"
        : "=r"(a) : "l"(p));
    return a;
}

__device__ __forceinline__ void ldsm4(uint32_t* r, uint32_t a) {
    asm volatile("ldmatrix.sync.aligned.m8n8.x4.shared.b16 {%0,%1,%2,%3}, [%4];"
        : "=r"(r[0]), "=r"(r[1]), "=r"(r[2]), "=r"(r[3]) : "r"(a));
}

__device__ __forceinline__ void mma16816(float* c, const uint32_t* a,
                                         const uint32_t* b) {
    asm volatile(
        "mma.sync.aligned.m16n8k16.row.col.f32.bf16.bf16.f32 "
        "{%0,%1,%2,%3}, {%4,%5,%6,%7}, {%8,%9}, {%0,%1,%2,%3};"
        : "+f"(c[0]), "+f"(c[1]), "+f"(c[2]), "+f"(c[3])
        : "r"(a[0]), "r"(a[1]), "r"(a[2]), "r"(a[3]), "r"(b[0]), "r"(b[1]));
}

// ---------------------------------------------------------------------------
// Core: acc[mt][nt][4] = A[0:128, 0:1024] @ B[0:128, 0:1024]^T  (bf16x3)
// A rows at Ahi/Alo (row-major, 1024 elems/row), B rows at Bhi/Blo.
// 8 warps: warpM = (wid&1)*64, warpN = (wid>>1)*32; warp tile 64x32.
// ---------------------------------------------------------------------------
__device__ __forceinline__ void gemm_bf16x3(
    const __nv_bfloat16* __restrict__ Ahi_g, const __nv_bfloat16* __restrict__ Alo_g,
    const __nv_bfloat16* __restrict__ Bhi_g, const __nv_bfloat16* __restrict__ Blo_g,
    char* sm, float acc[4][4][4])
{
    const int tid  = threadIdx.x;
    const int lane = tid & 31;
    const int wid  = tid >> 5;
    const int warpM = (wid & 1) << 6;
    const int warpN = (wid >> 1) << 5;
    const uint32_t smb = smem_u32(sm);

    #pragma unroll
    for (int a = 0; a < 4; a++)
        #pragma unroll
        for (int b = 0; b < 4; b++)
            #pragma unroll
            for (int k = 0; k < 4; k++) acc[a][b][k] = 0.f;

    // cooperative copy indexing: j = tid + (i&1)*256 in [0,512); row=j>>2, c16=j&3
    const int r0  = tid >> 2;          // 0..63
    const int c16 = tid & 3;           // 16B column within 64B row

    // ldmatrix lane addressing
    const int a_row = (lane & 7) + ((lane >> 3) & 1) * 8;
    const int a_kb  = ((lane >> 4) & 1) * 16;
    const int b_row = (lane & 7) + ((lane >> 4) & 1) * 8;
    const int b_kb  = ((lane >> 3) & 1) * 16;

    const __nv_bfloat16* gsrc[4] = {Ahi_g, Alo_g, Bhi_g, Blo_g};

    uint4 st[8];
    #pragma unroll
    for (int i = 0; i < 8; i++) {
        const int row = r0 + (i & 1) * 64;
        st[i] = *(const uint4*)&gsrc[i >> 1][(size_t)row * C_ + c16 * 8];
    }

    for (int c = 0; c < 32; c++) {
        #pragma unroll
        for (int i = 0; i < 8; i++) {
            const int row = r0 + (i & 1) * 64;
            *(uint4*)(sm + (i >> 1) * TILEB + row * 80 + c16 * 16) = st[i];
        }
        __syncthreads();

        if (c < 31) {
            #pragma unroll
            for (int i = 0; i < 8; i++) {
                const int row = r0 + (i & 1) * 64;
                st[i] = *(const uint4*)&gsrc[i >> 1][(size_t)row * C_ + (c + 1) * 32 + c16 * 8];
            }
        }

        #pragma unroll
        for (int ks = 0; ks < 2; ks++) {
            uint32_t ah[4][4], al[4][4], bh[2][4], bl[2][4];
            #pragma unroll
            for (int mt = 0; mt < 4; mt++) {
                const uint32_t off = (warpM + mt * 16 + a_row) * 80 + ks * 32 + a_kb;
                ldsm4(ah[mt], smb + off);              // Ahi tile at offset 0
                ldsm4(al[mt], smb + TILEB + off);      // Alo
            }
            #pragma unroll
            for (int p = 0; p < 2; p++) {
                const uint32_t off = (warpN + p * 16 + b_row) * 80 + ks * 32 + b_kb;
                ldsm4(bh[p], smb + 2 * TILEB + off);   // Bhi
                ldsm4(bl[p], smb + 3 * TILEB + off);   // Blo
            }
            #pragma unroll
            for (int mt = 0; mt < 4; mt++)
                #pragma unroll
                for (int nt = 0; nt < 4; nt++)
                    mma16816(acc[mt][nt], ah[mt], &bh[nt >> 1][(nt & 1) * 2]);
            #pragma unroll
            for (int mt = 0; mt < 4; mt++)
                #pragma unroll
                for (int nt = 0; nt < 4; nt++)
                    mma16816(acc[mt][nt], ah[mt], &bl[nt >> 1][(nt & 1) * 2]);
            #pragma unroll
            for (int mt = 0; mt < 4; mt++)
                #pragma unroll
                for (int nt = 0; nt < 4; nt++)
                    mma16816(acc[mt][nt], al[mt], &bh[nt >> 1][(nt & 1) * 2]);
        }
        __syncthreads();
    }
}

// ---------------------------------------------------------------------------
// hi/lo split conversion: sel picks destination (and source for sel 5 = g_A)
// ---------------------------------------------------------------------------
__global__ __launch_bounds__(256)
void cvt_kernel(const float* __restrict__ src, int sel, int n4)
{
    __nv_bfloat16 *hi, *lo;
    const float* s = src;
    switch (sel) {
        case 0: hi = g_xhi;    lo = g_xlo;    break;
        case 1: hi = g_wHi[0]; lo = g_wLo[0]; break;
        case 2: hi = g_wHi[1]; lo = g_wLo[1]; break;
        case 3: hi = g_wHi[2]; lo = g_wLo[2]; break;
        case 4: hi = g_woHi;   lo = g_woLo;   break;
        default: hi = g_aHi;   lo = g_aLo;    s = g_A; break;
    }
    const int i = blockIdx.x * 256 + threadIdx.x;
    if (i >= n4) return;
    const float4 v = *(const float4*)&s[i * 4];
    #pragma unroll
    for (int k = 0; k < 4; k++) {
        const float x = (&v.x)[k];
        const __nv_bfloat16 h = __float2bfloat16_rn(x);
        hi[i * 4 + k] = h;
        lo[i * 4 + k] = __float2bfloat16_rn(x - __bfloat162float(h));
    }
}

// ---------------------------------------------------------------------------
// RoPE tables
// ---------------------------------------------------------------------------
__global__ __launch_bounds__(512)
void rope_init_kernel()
{
    const int idx = blockIdx.x * blockDim.x + threadIdx.x;
    if (idx >= T_ * D_) return;
    const int t = idx >> 6;
    const int d = idx & 63;
    const float f = exp2f(-(float)(d & 31) * L32);
    float s, c;
    sincosf((float)t * f, &s, &c);
    g_cos[idx] = c;
    g_sin[idx] = s;
}

// ---------------------------------------------------------------------------
// QKV projection (+bias, +RoPE) via HMMA. grid (8, 32, 3)
// ---------------------------------------------------------------------------
__global__ __launch_bounds__(256, 1)
void qkv_mma_kernel(const float* __restrict__ bq, const float* __restrict__ bk,
                    const float* __restrict__ bv)
{
    __shared__ __align__(16) char sm[4 * TILEB];
    const int z = blockIdx.z;
    const float* bias = (z == 0) ? bq : (z == 1) ? bk : bv;
    float* dst        = (z == 0) ? g_Q : (z == 1) ? g_K : g_V;
    const bool rope   = (z < 2);

    const int m0 = blockIdx.y * 128;
    const int n0 = blockIdx.x * 128;

    float acc[4][4][4];
    gemm_bf16x3(g_xhi + (size_t)m0 * C_, g_xlo + (size_t)m0 * C_,
                g_wHi[z] + (size_t)n0 * C_, g_wLo[z] + (size_t)n0 * C_,
                sm, acc);

    const int lane = threadIdx.x & 31, wid = threadIdx.x >> 5;
    const int warpM = (wid & 1) << 6, warpN = (wid >> 1) << 5;
    const int g = lane >> 2;
    const int ncol = warpN + (lane & 3) * 2;

    #pragma unroll
    for (int mt = 0; mt < 4; mt++) {
        #pragma unroll
        for (int hf = 0; hf < 2; hf++) {
            const int m = m0 + warpM + mt * 16 + g + hf * 8;
            const int b = m >> 11, t = m & 2047;
            const float* cosr = &g_cos[t * 64];
            const float* sinr = &g_sin[t * 64];
            #pragma unroll
            for (int nt = 0; nt < 4; nt++) {
                const int n = n0 + ncol + nt * 8;
                const int h = n >> 6, d = n & 63;
                float v0 = acc[mt][nt][hf * 2 + 0] + bias[n];
                float v1 = acc[mt][nt][hf * 2 + 1] + bias[n + 1];
                if (rope) {
                    const float ce = cosr[d],     se = sinr[d];
                    const float co = cosr[d + 1], so = sinr[d + 1];
                    const float w0 = v0 * ce - v1 * se;
                    const float w1 = v1 * co + v0 * so;
                    v0 = w0; v1 = w1;
                }
                *(float2*)&dst[(size_t)((b * H_ + h) * T_ + t) * D_ + d] =
                    make_float2(v0, v1);
            }
        }
    }
}

// ---------------------------------------------------------------------------
// Output projection via HMMA: out = A @ wo^T + bo. grid (8, 32)
// ---------------------------------------------------------------------------
__global__ __launch_bounds__(256, 1)
void oproj_mma_kernel(const float* __restrict__ bo, float* __restrict__ out)
{
    __shared__ __align__(16) char sm[4 * TILEB];
    const int m0 = blockIdx.y * 128;
    const int n0 = blockIdx.x * 128;

    float acc[4][4][4];
    gemm_bf16x3(g_aHi + (size_t)m0 * C_, g_aLo + (size_t)m0 * C_,
                g_woHi + (size_t)n0 * C_, g_woLo + (size_t)n0 * C_,
                sm, acc);

    const int lane = threadIdx.x & 31, wid = threadIdx.x >> 5;
    const int warpM = (wid & 1) << 6, warpN = (wid >> 1) << 5;
    const int g = lane >> 2;
    const int ncol = warpN + (lane & 3) * 2;

    #pragma unroll
    for (int mt = 0; mt < 4; mt++) {
        #pragma unroll
        for (int hf = 0; hf < 2; hf++) {
            const int m = m0 + warpM + mt * 16 + g + hf * 8;
            #pragma unroll
            for (int nt = 0; nt < 4; nt++) {
                const int n = n0 + ncol + nt * 8;
                const float v0 = acc[mt][nt][hf * 2 + 0] + bo[n];
                const float v1 = acc[mt][nt][hf * 2 + 1] + bo[n + 1];
                *(float2*)&out[(size_t)m * C_ + n] = make_float2(v0, v1);
            }
        }
    }
}

// ---------------------------------------------------------------------------
// Flash attention (unchanged from passing R1 kernel)
// ---------------------------------------------------------------------------
__global__ __launch_bounds__(128)
void attn_kernel()
{
    __shared__ float Qt[64][68];
    __shared__ float Kt[64][36];
    __shared__ float Vs[32][68];
    __shared__ float Pt[32][68];
    __shared__ float m_s[64], l_s[64], alpha_s[64];
    __shared__ float pbuf[2][64];

    const int tid = threadIdx.x;
    const int bh  = blockIdx.y;
    const int q0  = blockIdx.x * 64;
    const float* Qg = g_Q + (size_t)bh * T_ * D_;
    const float* Kg = g_K + (size_t)bh * T_ * D_;
    const float* Vg = g_V + (size_t)bh * T_ * D_;

    const int tk = tid & 7;
    const int tq = tid >> 3;

    #pragma unroll
    for (int e = tid; e < 64 * 16; e += 128) {
        const int row = e >> 4, c4 = (e & 15) << 2;
        float4 v = *(const float4*)&Qg[(size_t)(q0 + row) * D_ + c4];
        Qt[c4 + 0][row] = v.x * 0.125f;
        Qt[c4 + 1][row] = v.y * 0.125f;
        Qt[c4 + 2][row] = v.z * 0.125f;
        Qt[c4 + 3][row] = v.w * 0.125f;
    }
    if (tid < 64) { m_s[tid] = -INFINITY; l_s[tid] = 0.f; }

    float O[4][8];
    #pragma unroll
    for (int i = 0; i < 4; i++)
        #pragma unroll
        for (int j = 0; j < 8; j++) O[i][j] = 0.f;
    __syncthreads();

    for (int kv0 = 0; kv0 < T_; kv0 += 32) {
        #pragma unroll
        for (int e = tid; e < 32 * 16; e += 128) {
            const int row = e >> 4, c4 = (e & 15) << 2;
            float4 kvv = *(const float4*)&Kg[(size_t)(kv0 + row) * D_ + c4];
            Kt[c4 + 0][row] = kvv.x; Kt[c4 + 1][row] = kvv.y;
            Kt[c4 + 2][row] = kvv.z; Kt[c4 + 3][row] = kvv.w;
            float4 vv = *(const float4*)&Vg[(size_t)(kv0 + row) * D_ + c4];
            *(float4*)&Vs[row][c4] = vv;
        }
        __syncthreads();

        float s[4][4];
        #pragma unroll
        for (int i = 0; i < 4; i++)
            #pragma unroll
            for (int j = 0; j < 4; j++) s[i][j] = 0.f;
        #pragma unroll 8
        for (int d = 0; d < 64; d++) {
            float4 a4 = *(const float4*)&Qt[d][4 * tq];
            float4 b4 = *(const float4*)&Kt[d][4 * tk];
            float a[4] = {a4.x, a4.y, a4.z, a4.w};
            float b[4] = {b4.x, b4.y, b4.z, b4.w};
            #pragma unroll
            for (int i = 0; i < 4; i++)
                #pragma unroll
                for (int j = 0; j < 4; j++)
                    s[i][j] += a[i] * b[j];
        }
        #pragma unroll
        for (int i = 0; i < 4; i++)
            #pragma unroll
            for (int j = 0; j < 4; j++)
                Pt[4 * tk + j][4 * tq + i] = s[i][j];
        __syncthreads();

        const int r  = tid & 63;
        const int hh = tid >> 6;
        float mx = -INFINITY;
        #pragma unroll
        for (int j = 0; j < 16; j++)
            mx = fmaxf(mx, Pt[hh * 16 + j][r]);
        pbuf[hh][r] = mx;
        __syncthreads();
        if (tid < 64) {
            const float nm = fmaxf(m_s[tid], fmaxf(pbuf[0][tid], pbuf[1][tid]));
            alpha_s[tid] = expf(m_s[tid] - nm);
            m_s[tid] = nm;
        }
        __syncthreads();
        {
            const float mrow = m_s[r];
            float ssum = 0.f;
            #pragma unroll
            for (int j = 0; j < 16; j++) {
                const int kv = hh * 16 + j;
                const float e = expf(Pt[kv][r] - mrow);
                Pt[kv][r] = e;
                ssum += e;
            }
            pbuf[hh][r] = ssum;
        }
        __syncthreads();
        if (tid < 64)
            l_s[tid] = l_s[tid] * alpha_s[tid] + pbuf[0][tid] + pbuf[1][tid];
        __syncthreads();

        float al[4];
        #pragma unroll
        for (int i = 0; i < 4; i++) al[i] = alpha_s[4 * tq + i];
        #pragma unroll
        for (int i = 0; i < 4; i++)
            #pragma unroll
            for (int j = 0; j < 8; j++) O[i][j] *= al[i];

        #pragma unroll 4
        for (int kv = 0; kv < 32; kv++) {
            float4 p4 = *(const float4*)&Pt[kv][4 * tq];
            float4 v0 = *(const float4*)&Vs[kv][8 * tk];
            float4 v1 = *(const float4*)&Vs[kv][8 * tk + 4];
            float p[4] = {p4.x, p4.y, p4.z, p4.w};
            float vv[8] = {v0.x, v0.y, v0.z, v0.w, v1.x, v1.y, v1.z, v1.w};
            #pragma unroll
            for (int i = 0; i < 4; i++)
                #pragma unroll
                for (int j = 0; j < 8; j++)
                    O[i][j] += p[i] * vv[j];
        }
        __syncthreads();
    }

    const int b = bh >> 4, h = bh & 15;
    #pragma unroll
    for (int i = 0; i < 4; i++) {
        const float linv = 1.f / l_s[4 * tq + i];
        const int t = q0 + 4 * tq + i;
        float* dstp = &g_A[(size_t)(b * T_ + t) * C_ + h * D_ + 8 * tk];
        float4 o0 = make_float4(O[i][0] * linv, O[i][1] * linv,
                                O[i][2] * linv, O[i][3] * linv);
        float4 o1 = make_float4(O[i][4] * linv, O[i][5] * linv,
                                O[i][6] * linv, O[i][7] * linv);
        *(float4*)&dstp[0] = o0;
        *(float4*)&dstp[4] = o1;
    }
}

// ---------------------------------------------------------------------------
extern "C" void kernel_launch(void* const* d_in, const int* in_sizes, int n_in,
                              void* d_out, int out_size)
{
    const float* x  = (const float*)d_in[0];
    const float* wq = (const float*)d_in[1];
    const float* bq = (const float*)d_in[2];
    const float* wk = (const float*)d_in[3];
    const float* bk = (const float*)d_in[4];
    const float* wv = (const float*)d_in[5];
    const float* bv = (const float*)d_in[6];
    const float* wo = (const float*)d_in[7];
    const float* bo = (const float*)d_in[8];
    float* out = (float*)d_out;

    rope_init_kernel<<<(T_ * D_ + 511) / 512, 512>>>();

    const int nx4 = M_ * C_ / 4;     // 1M float4
    const int nw4 = C_ * C_ / 4;     // 256K float4
    cvt_kernel<<<(nx4 + 255) / 256, 256>>>(x,  0, nx4);
    cvt_kernel<<<(nw4 + 255) / 256, 256>>>(wq, 1, nw4);
    cvt_kernel<<<(nw4 + 255) / 256, 256>>>(wk, 2, nw4);
    cvt_kernel<<<(nw4 + 255) / 256, 256>>>(wv, 3, nw4);
    cvt_kernel<<<(nw4 + 255) / 256, 256>>>(wo, 4, nw4);

    dim3 gqkv(C_ / 128, M_ / 128, 3);       // (8, 32, 3)
    qkv_mma_kernel<<<gqkv, 256>>>(bq, bk, bv);

    dim3 gattn(T_ / 64, B_ * H_);           // (32, 32)
    attn_kernel<<<gattn, 128>>>();

    cvt_kernel<<<(nx4 + 255) / 256, 256>>>(x, 5, nx4);   // src overridden to g_A

    dim3 gout(C_ / 128, M_ / 128);          // (8, 32)
    oproj_mma_kernel<<<gout, 256>>>(bo, out);
}

// round 12
// speedup vs baseline: 2.8751x; 2.1279x over previous
#include <cuda_runtime.h>
#include <cuda_bf16.h>
#include <math.h>
#include <stdint.h>

// Problem constants
#define B_ 2
#define T_ 2048
#define C_ 1024
#define H_ 16
#define D_ 64
#define M_ (B_*T_)

// log2(10000)/32
#define L32 0.4152410118609203f

// Scratch (device globals)
__device__ float g_cos[T_*D_];
__device__ float g_sin[T_*D_];

// bf16 hi/lo split operands
__device__ __nv_bfloat16 g_xhi[M_*C_], g_xlo[M_*C_];
__device__ __nv_bfloat16 g_wHi[3][C_*C_], g_wLo[3][C_*C_];
__device__ __nv_bfloat16 g_woHi[C_*C_], g_woLo[C_*C_];
__device__ __nv_bfloat16 g_aHi[M_*C_], g_aLo[M_*C_];

// RoPE'd Q/K/V, bf16 hi/lo, [bh][t][d]; Q pre-scaled by 1/8
__device__ __nv_bfloat16 g_Qhi[B_*H_*T_*D_], g_Qlo[B_*H_*T_*D_];
__device__ __nv_bfloat16 g_Khi[B_*H_*T_*D_], g_Klo[B_*H_*T_*D_];
__device__ __nv_bfloat16 g_Vhi[B_*H_*T_*D_], g_Vlo[B_*H_*T_*D_];

#define TILEB (128*80)   // GEMM smem tile bytes

__device__ __forceinline__ uint32_t smem_u32(const void* p) {
    uint32_t a;
    asm("{ .reg .u64 t; cvta.to.shared.u64 t, %1; cvt.u32.u64 %0, t; }"
        : "=r"(a) : "l"(p));
    return a;
}

__device__ __forceinline__ void ldsm4(uint32_t* r, uint32_t a) {
    asm volatile("ldmatrix.sync.aligned.m8n8.x4.shared.b16 {%0,%1,%2,%3}, [%4];"
        : "=r"(r[0]), "=r"(r[1]), "=r"(r[2]), "=r"(r[3]) : "r"(a));
}
__device__ __forceinline__ void ldsm4t(uint32_t* r, uint32_t a) {
    asm volatile("ldmatrix.sync.aligned.m8n8.x4.trans.shared.b16 {%0,%1,%2,%3}, [%4];"
        : "=r"(r[0]), "=r"(r[1]), "=r"(r[2]), "=r"(r[3]) : "r"(a));
}

__device__ __forceinline__ void mma16816(float* c, const uint32_t* a,
                                         const uint32_t* b) {
    asm volatile(
        "mma.sync.aligned.m16n8k16.row.col.f32.bf16.bf16.f32 "
        "{%0,%1,%2,%3}, {%4,%5,%6,%7}, {%8,%9}, {%0,%1,%2,%3};"
        : "+f"(c[0]), "+f"(c[1]), "+f"(c[2]), "+f"(c[3])
        : "r"(a[0]), "r"(a[1]), "r"(a[2]), "r"(a[3]), "r"(b[0]), "r"(b[1]));
}

// exp on the FMA pipe (no MUFU): 2^f Taylor deg-5, rel err ~2e-6, x in [-80,0]
__device__ __forceinline__ float fast_exp(float x) {
    x = fmaxf(x, -80.f);
    const float y = x * 1.4426950408889634f;
    const float mm = __fadd_rn(y, 12582912.f);   // round-to-nearest magic
    const float i  = __fadd_rn(mm, -12582912.f);
    const float f  = y - i;
    float p = 1.3333558146e-3f;
    p = fmaf(p, f, 9.6181291794e-3f);
    p = fmaf(p, f, 5.5504108664e-2f);
    p = fmaf(p, f, 2.4022650695e-1f);
    p = fmaf(p, f, 6.9314718056e-1f);
    p = fmaf(p, f, 1.0f);
    const int ii = __float_as_int(mm) - 0x4B400000;       // = (int)i
    return p * __int_as_float((ii + 127) << 23);
}

// ---------------------------------------------------------------------------
// GEMM core (unchanged from passing R5): 128x128 @ K=1024, bf16x3 HMMA
// ---------------------------------------------------------------------------
__device__ __forceinline__ void gemm_bf16x3(
    const __nv_bfloat16* __restrict__ Ahi_g, const __nv_bfloat16* __restrict__ Alo_g,
    const __nv_bfloat16* __restrict__ Bhi_g, const __nv_bfloat16* __restrict__ Blo_g,
    char* sm, float acc[4][4][4])
{
    const int tid  = threadIdx.x;
    const int lane = tid & 31;
    const int wid  = tid >> 5;
    const int warpM = (wid & 1) << 6;
    const int warpN = (wid >> 1) << 5;
    const uint32_t smb = smem_u32(sm);

    #pragma unroll
    for (int a = 0; a < 4; a++)
        #pragma unroll
        for (int b = 0; b < 4; b++)
            #pragma unroll
            for (int k = 0; k < 4; k++) acc[a][b][k] = 0.f;

    const int r0  = tid >> 2;
    const int c16 = tid & 3;

    const int a_row = (lane & 7) + ((lane >> 3) & 1) * 8;
    const int a_kb  = ((lane >> 4) & 1) * 16;
    const int b_row = (lane & 7) + ((lane >> 4) & 1) * 8;
    const int b_kb  = ((lane >> 3) & 1) * 16;

    const __nv_bfloat16* gsrc[4] = {Ahi_g, Alo_g, Bhi_g, Blo_g};

    uint4 st[8];
    #pragma unroll
    for (int i = 0; i < 8; i++) {
        const int row = r0 + (i & 1) * 64;
        st[i] = *(const uint4*)&gsrc[i >> 1][(size_t)row * C_ + c16 * 8];
    }

    for (int c = 0; c < 32; c++) {
        #pragma unroll
        for (int i = 0; i < 8; i++) {
            const int row = r0 + (i & 1) * 64;
            *(uint4*)(sm + (i >> 1) * TILEB + row * 80 + c16 * 16) = st[i];
        }
        __syncthreads();

        if (c < 31) {
            #pragma unroll
            for (int i = 0; i < 8; i++) {
                const int row = r0 + (i & 1) * 64;
                st[i] = *(const uint4*)&gsrc[i >> 1][(size_t)row * C_ + (c + 1) * 32 + c16 * 8];
            }
        }

        #pragma unroll
        for (int ks = 0; ks < 2; ks++) {
            uint32_t ah[4][4], al[4][4], bh[2][4], bl[2][4];
            #pragma unroll
            for (int mt = 0; mt < 4; mt++) {
                const uint32_t off = (warpM + mt * 16 + a_row) * 80 + ks * 32 + a_kb;
                ldsm4(ah[mt], smb + off);
                ldsm4(al[mt], smb + TILEB + off);
            }
            #pragma unroll
            for (int p = 0; p < 2; p++) {
                const uint32_t off = (warpN + p * 16 + b_row) * 80 + ks * 32 + b_kb;
                ldsm4(bh[p], smb + 2 * TILEB + off);
                ldsm4(bl[p], smb + 3 * TILEB + off);
            }
            #pragma unroll
            for (int mt = 0; mt < 4; mt++)
                #pragma unroll
                for (int nt = 0; nt < 4; nt++)
                    mma16816(acc[mt][nt], ah[mt], &bh[nt >> 1][(nt & 1) * 2]);
            #pragma unroll
            for (int mt = 0; mt < 4; mt++)
                #pragma unroll
                for (int nt = 0; nt < 4; nt++)
                    mma16816(acc[mt][nt], ah[mt], &bl[nt >> 1][(nt & 1) * 2]);
            #pragma unroll
            for (int mt = 0; mt < 4; mt++)
                #pragma unroll
                for (int nt = 0; nt < 4; nt++)
                    mma16816(acc[mt][nt], al[mt], &bh[nt >> 1][(nt & 1) * 2]);
        }
        __syncthreads();
    }
}

// ---------------------------------------------------------------------------
__global__ __launch_bounds__(256)
void cvt_kernel(const float* __restrict__ src, int sel, int n4)
{
    __nv_bfloat16 *hi, *lo;
    switch (sel) {
        case 0: hi = g_xhi;    lo = g_xlo;    break;
        case 1: hi = g_wHi[0]; lo = g_wLo[0]; break;
        case 2: hi = g_wHi[1]; lo = g_wLo[1]; break;
        case 3: hi = g_wHi[2]; lo = g_wLo[2]; break;
        default: hi = g_woHi;  lo = g_woLo;   break;
    }
    const int i = blockIdx.x * 256 + threadIdx.x;
    if (i >= n4) return;
    const float4 v = *(const float4*)&src[i * 4];
    #pragma unroll
    for (int k = 0; k < 4; k++) {
        const float x = (&v.x)[k];
        const __nv_bfloat16 h = __float2bfloat16_rn(x);
        hi[i * 4 + k] = h;
        lo[i * 4 + k] = __float2bfloat16_rn(x - __bfloat162float(h));
    }
}

__global__ __launch_bounds__(512)
void rope_init_kernel()
{
    const int idx = blockIdx.x * blockDim.x + threadIdx.x;
    if (idx >= T_ * D_) return;
    const int t = idx >> 6;
    const int d = idx & 63;
    const float f = exp2f(-(float)(d & 31) * L32);
    float s, c;
    sincosf((float)t * f, &s, &c);
    g_cos[idx] = c;
    g_sin[idx] = s;
}

// ---------------------------------------------------------------------------
// QKV projection: epilogue emits bf16 hi/lo Q/K/V, RoPE'd, Q scaled by 1/8
// ---------------------------------------------------------------------------
__global__ __launch_bounds__(256, 1)
void qkv_mma_kernel(const float* __restrict__ bq, const float* __restrict__ bk,
                    const float* __restrict__ bv)
{
    __shared__ __align__(16) char sm[4 * TILEB];
    const int z = blockIdx.z;
    const float* bias = (z == 0) ? bq : (z == 1) ? bk : bv;
    __nv_bfloat16* dhi = (z == 0) ? g_Qhi : (z == 1) ? g_Khi : g_Vhi;
    __nv_bfloat16* dlo = (z == 0) ? g_Qlo : (z == 1) ? g_Klo : g_Vlo;
    const bool rope  = (z < 2);
    const float qscl = (z == 0) ? 0.125f : 1.0f;

    const int m0 = blockIdx.y * 128;
    const int n0 = blockIdx.x * 128;

    float acc[4][4][4];
    gemm_bf16x3(g_xhi + (size_t)m0 * C_, g_xlo + (size_t)m0 * C_,
                g_wHi[z] + (size_t)n0 * C_, g_wLo[z] + (size_t)n0 * C_,
                sm, acc);

    const int lane = threadIdx.x & 31, wid = threadIdx.x >> 5;
    const int warpM = (wid & 1) << 6, warpN = (wid >> 1) << 5;
    const int g = lane >> 2;
    const int ncol = warpN + (lane & 3) * 2;

    #pragma unroll
    for (int mt = 0; mt < 4; mt++) {
        #pragma unroll
        for (int hf = 0; hf < 2; hf++) {
            const int m = m0 + warpM + mt * 16 + g + hf * 8;
            const int b = m >> 11, t = m & 2047;
            const float* cosr = &g_cos[t * 64];
            const float* sinr = &g_sin[t * 64];
            #pragma unroll
            for (int nt = 0; nt < 4; nt++) {
                const int n = n0 + ncol + nt * 8;
                const int h = n >> 6, d = n & 63;
                float v0 = acc[mt][nt][hf * 2 + 0] + bias[n];
                float v1 = acc[mt][nt][hf * 2 + 1] + bias[n + 1];
                if (rope) {
                    const float ce = cosr[d],     se = sinr[d];
                    const float co = cosr[d + 1], so = sinr[d + 1];
                    const float w0 = v0 * ce - v1 * se;
                    const float w1 = v1 * co + v0 * so;
                    v0 = w0; v1 = w1;
                }
                v0 *= qscl; v1 *= qscl;
                const __nv_bfloat16 h0 = __float2bfloat16_rn(v0);
                const __nv_bfloat16 h1 = __float2bfloat16_rn(v1);
                const __nv_bfloat16 l0 = __float2bfloat16_rn(v0 - __bfloat162float(h0));
                const __nv_bfloat16 l1 = __float2bfloat16_rn(v1 - __bfloat162float(h1));
                const size_t idx = (size_t)((b * H_ + h) * T_ + t) * D_ + d;
                *(__nv_bfloat162*)&dhi[idx] = __nv_bfloat162{h0, h1};
                *(__nv_bfloat162*)&dlo[idx] = __nv_bfloat162{l0, l1};
            }
        }
    }
}

// ---------------------------------------------------------------------------
// Flash attention via HMMA bf16x3. CTA: 128 q-rows x one (b,h). 8 warps.
// Writes context directly as bf16 hi/lo into g_aHi/g_aLo.
// ---------------------------------------------------------------------------
#define AQH 0u
#define AQL 18432u
#define AKH 36864u
#define AKL 46080u
#define AVH 55296u
#define AVL 64512u
#define ASMEM 73728

__global__ __launch_bounds__(256, 1)
void attn_mma_kernel()
{
    extern __shared__ char sm[];
    const uint32_t smb = smem_u32(sm);
    const int tid = threadIdx.x, lane = tid & 31, wid = tid >> 5;
    const int bh = blockIdx.y;
    const int q0 = blockIdx.x * 128;
    const int warpM = wid * 16;
    const size_t base = (size_t)bh * T_ * D_;

    const int g = lane >> 2, t4 = lane & 3;
    const int a_row = lane & 15,                      a_koff = (lane >> 4) * 16;
    const int b_row = (lane & 7) + ((lane >> 4) & 1) * 8, b_koff = ((lane >> 3) & 1) * 16;
    const int v_row = (lane & 7) + ((lane >> 3) & 1) * 8, v_doff = ((lane >> 4) & 1) * 16;

    // Load Q tile (hi/lo): 2 buffers x 128 rows x 8 uint4 (128B/row) = 2048 uint4
    #pragma unroll
    for (int k2 = 0; k2 < 8; k2++) {
        const int u = tid + k2 * 256;
        const __nv_bfloat16* src = (u < 1024) ? g_Qhi : g_Qlo;
        const uint32_t doff = (u < 1024) ? AQH : AQL;
        const int rem = u & 1023, row = rem >> 3, ch = rem & 7;
        const uint4 v = *(const uint4*)&src[base + (size_t)(q0 + row) * 64 + ch * 8];
        *(uint4*)(sm + doff + row * 144 + ch * 16) = v;
    }

    float o[8][4];
    #pragma unroll
    for (int i = 0; i < 8; i++)
        #pragma unroll
        for (int j = 0; j < 4; j++) o[i][j] = 0.f;
    float m0r = -1e30f, m1r = -1e30f, l0 = 0.f, l1 = 0.f;

    // prefetch first K/V tile: 4 buffers x 64 rows x 8 uint4 = 2048 uint4
    uint4 pre[8];
    #pragma unroll
    for (int k2 = 0; k2 < 8; k2++) {
        const int u = tid + k2 * 256;
        const __nv_bfloat16* src = (u < 512) ? g_Khi : (u < 1024) ? g_Klo
                                 : (u < 1536) ? g_Vhi : g_Vlo;
        const int rem = u & 511, row = rem >> 3, ch = rem & 7;
        pre[k2] = *(const uint4*)&src[base + (size_t)row * 64 + ch * 8];
    }

    for (int c = 0; c < 32; c++) {
        __syncthreads();   // previous iteration's smem reads done
        #pragma unroll
        for (int k2 = 0; k2 < 8; k2++) {
            const int u = tid + k2 * 256;
            const uint32_t doff = (u < 512) ? AKH : (u < 1024) ? AKL
                                : (u < 1536) ? AVH : AVL;
            const int rem = u & 511, row = rem >> 3, ch = rem & 7;
            *(uint4*)(sm + doff + row * 144 + ch * 16) = pre[k2];
        }
        __syncthreads();
        if (c < 31) {
            const int kvn = (c + 1) * 64;
            #pragma unroll
            for (int k2 = 0; k2 < 8; k2++) {
                const int u = tid + k2 * 256;
                const __nv_bfloat16* src = (u < 512) ? g_Khi : (u < 1024) ? g_Klo
                                         : (u < 1536) ? g_Vhi : g_Vlo;
                const int rem = u & 511, row = rem >> 3, ch = rem & 7;
                pre[k2] = *(const uint4*)&src[base + (size_t)(kvn + row) * 64 + ch * 8];
            }
        }

        // ---- S = Q*K^T (128x64, k=64), bf16x3 ----
        float s[8][4];
        #pragma unroll
        for (int i = 0; i < 8; i++)
            #pragma unroll
            for (int j = 0; j < 4; j++) s[i][j] = 0.f;

        #pragma unroll
        for (int kb = 0; kb < 4; kb++) {
            uint32_t qh[4], ql[4], kh[4][4], kl[4][4];
            const uint32_t qoff = (warpM + a_row) * 144 + kb * 32 + a_koff;
            ldsm4(qh, smb + AQH + qoff);
            ldsm4(ql, smb + AQL + qoff);
            #pragma unroll
            for (int p = 0; p < 4; p++) {
                const uint32_t koff = (p * 16 + b_row) * 144 + kb * 32 + b_koff;
                ldsm4(kh[p], smb + AKH + koff);
                ldsm4(kl[p], smb + AKL + koff);
            }
            #pragma unroll
            for (int nt = 0; nt < 8; nt++)
                mma16816(s[nt], qh, &kh[nt >> 1][(nt & 1) * 2]);
            #pragma unroll
            for (int nt = 0; nt < 8; nt++)
                mma16816(s[nt], qh, &kl[nt >> 1][(nt & 1) * 2]);
            #pragma unroll
            for (int nt = 0; nt < 8; nt++)
                mma16816(s[nt], ql, &kh[nt >> 1][(nt & 1) * 2]);
        }

        // ---- online softmax on fragments ----
        float mt0 = -1e30f, mt1 = -1e30f;
        #pragma unroll
        for (int nt = 0; nt < 8; nt++) {
            mt0 = fmaxf(mt0, fmaxf(s[nt][0], s[nt][1]));
            mt1 = fmaxf(mt1, fmaxf(s[nt][2], s[nt][3]));
        }
        mt0 = fmaxf(mt0, __shfl_xor_sync(0xffffffffu, mt0, 1));
        mt0 = fmaxf(mt0, __shfl_xor_sync(0xffffffffu, mt0, 2));
        mt1 = fmaxf(mt1, __shfl_xor_sync(0xffffffffu, mt1, 1));
        mt1 = fmaxf(mt1, __shfl_xor_sync(0xffffffffu, mt1, 2));
        const float nm0 = fmaxf(m0r, mt0), nm1 = fmaxf(m1r, mt1);
        const float al0 = fast_exp(m0r - nm0), al1 = fast_exp(m1r - nm1);
        m0r = nm0; m1r = nm1;

        float sum0 = 0.f, sum1 = 0.f;
        #pragma unroll
        for (int nt = 0; nt < 8; nt++) {
            s[nt][0] = fast_exp(s[nt][0] - nm0);
            s[nt][1] = fast_exp(s[nt][1] - nm0);
            s[nt][2] = fast_exp(s[nt][2] - nm1);
            s[nt][3] = fast_exp(s[nt][3] - nm1);
            sum0 += s[nt][0] + s[nt][1];
            sum1 += s[nt][2] + s[nt][3];
        }
        sum0 += __shfl_xor_sync(0xffffffffu, sum0, 1);
        sum0 += __shfl_xor_sync(0xffffffffu, sum0, 2);
        sum1 += __shfl_xor_sync(0xffffffffu, sum1, 1);
        sum1 += __shfl_xor_sync(0xffffffffu, sum1, 2);
        l0 = l0 * al0 + sum0;
        l1 = l1 * al1 + sum1;

        #pragma unroll
        for (int nt = 0; nt < 8; nt++) {
            o[nt][0] *= al0; o[nt][1] *= al0;
            o[nt][2] *= al1; o[nt][3] *= al1;
        }

        // ---- O += P*V (128x64, k=64), P hi/lo in registers ----
        #pragma unroll
        for (int kb2 = 0; kb2 < 4; kb2++) {
            const int j = 2 * kb2;
            uint32_t ah[4], al[4];
            {
                const float* p0 = s[j];
                const float* p1 = s[j + 1];
                __nv_bfloat16 h;
                float r;
                __nv_bfloat162 t2;
                h = __float2bfloat16_rn(p0[0]); r = p0[0] - __bfloat162float(h);
                t2.x = h; t2.y = __float2bfloat16_rn(p0[1]);
                __nv_bfloat162 u2; u2.x = __float2bfloat16_rn(r);
                r = p0[1] - __bfloat162float(t2.y); u2.y = __float2bfloat16_rn(r);
                ah[0] = *(uint32_t*)&t2; al[0] = *(uint32_t*)&u2;
                h = __float2bfloat16_rn(p0[2]); r = p0[2] - __bfloat162float(h);
                t2.x = h; t2.y = __float2bfloat16_rn(p0[3]);
                u2.x = __float2bfloat16_rn(r);
                r = p0[3] - __bfloat162float(t2.y); u2.y = __float2bfloat16_rn(r);
                ah[1] = *(uint32_t*)&t2; al[1] = *(uint32_t*)&u2;
                h = __float2bfloat16_rn(p1[0]); r = p1[0] - __bfloat162float(h);
                t2.x = h; t2.y = __float2bfloat16_rn(p1[1]);
                u2.x = __float2bfloat16_rn(r);
                r = p1[1] - __bfloat162float(t2.y); u2.y = __float2bfloat16_rn(r);
                ah[2] = *(uint32_t*)&t2; al[2] = *(uint32_t*)&u2;
                h = __float2bfloat16_rn(p1[2]); r = p1[2] - __bfloat162float(h);
                t2.x = h; t2.y = __float2bfloat16_rn(p1[3]);
                u2.x = __float2bfloat16_rn(r);
                r = p1[3] - __bfloat162float(t2.y); u2.y = __float2bfloat16_rn(r);
                ah[3] = *(uint32_t*)&t2; al[3] = *(uint32_t*)&u2;
            }
            uint32_t vh[4][4], vl[4][4];
            #pragma unroll
            for (int dp = 0; dp < 4; dp++) {
                const uint32_t voff = (kb2 * 16 + v_row) * 144 + dp * 32 + v_doff;
                ldsm4t(vh[dp], smb + AVH + voff);
                ldsm4t(vl[dp], smb + AVL + voff);
            }
            #pragma unroll
            for (int nt = 0; nt < 8; nt++)
                mma16816(o[nt], ah, &vh[nt >> 1][(nt & 1) * 2]);
            #pragma unroll
            for (int nt = 0; nt < 8; nt++)
                mma16816(o[nt], ah, &vl[nt >> 1][(nt & 1) * 2]);
            #pragma unroll
            for (int nt = 0; nt < 8; nt++)
                mma16816(o[nt], al, &vh[nt >> 1][(nt & 1) * 2]);
        }
    }

    // ---- finalize + write bf16 hi/lo context ----
    const int b = bh >> 4, h = bh & 15;
    const float inv0 = 1.f / l0, inv1 = 1.f / l1;
    const int t0 = q0 + warpM + g;
    const int t1 = t0 + 8;
    const size_t r0a = (size_t)(b * T_ + t0) * C_ + h * 64;
    const size_t r1a = (size_t)(b * T_ + t1) * C_ + h * 64;
    #pragma unroll
    for (int nt = 0; nt < 8; nt++) {
        const int d = nt * 8 + 2 * t4;
        float v0 = o[nt][0] * inv0, v1 = o[nt][1] * inv0;
        float v2 = o[nt][2] * inv1, v3 = o[nt][3] * inv1;
        __nv_bfloat16 h0 = __float2bfloat16_rn(v0), h1 = __float2bfloat16_rn(v1);
        __nv_bfloat16 h2 = __float2bfloat16_rn(v2), h3 = __float2bfloat16_rn(v3);
        *(__nv_bfloat162*)&g_aHi[r0a + d] = __nv_bfloat162{h0, h1};
        *(__nv_bfloat162*)&g_aHi[r1a + d] = __nv_bfloat162{h2, h3};
        *(__nv_bfloat162*)&g_aLo[r0a + d] = __nv_bfloat162{
            __float2bfloat16_rn(v0 - __bfloat162float(h0)),
            __float2bfloat16_rn(v1 - __bfloat162float(h1))};
        *(__nv_bfloat162*)&g_aLo[r1a + d] = __nv_bfloat162{
            __float2bfloat16_rn(v2 - __bfloat162float(h2)),
            __float2bfloat16_rn(v3 - __bfloat162float(h3))};
    }
}

// ---------------------------------------------------------------------------
// Output projection (unchanged from passing R5)
// ---------------------------------------------------------------------------
__global__ __launch_bounds__(256, 1)
void oproj_mma_kernel(const float* __restrict__ bo, float* __restrict__ out)
{
    __shared__ __align__(16) char sm[4 * TILEB];
    const int m0 = blockIdx.y * 128;
    const int n0 = blockIdx.x * 128;

    float acc[4][4][4];
    gemm_bf16x3(g_aHi + (size_t)m0 * C_, g_aLo + (size_t)m0 * C_,
                g_woHi + (size_t)n0 * C_, g_woLo + (size_t)n0 * C_,
                sm, acc);

    const int lane = threadIdx.x & 31, wid = threadIdx.x >> 5;
    const int warpM = (wid & 1) << 6, warpN = (wid >> 1) << 5;
    const int g = lane >> 2;
    const int ncol = warpN + (lane & 3) * 2;

    #pragma unroll
    for (int mt = 0; mt < 4; mt++) {
        #pragma unroll
        for (int hf = 0; hf < 2; hf++) {
            const int m = m0 + warpM + mt * 16 + g + hf * 8;
            #pragma unroll
            for (int nt = 0; nt < 4; nt++) {
                const int n = n0 + ncol + nt * 8;
                const float v0 = acc[mt][nt][hf * 2 + 0] + bo[n];
                const float v1 = acc[mt][nt][hf * 2 + 1] + bo[n + 1];
                *(float2*)&out[(size_t)m * C_ + n] = make_float2(v0, v1);
            }
        }
    }
}

// ---------------------------------------------------------------------------
extern "C" void kernel_launch(void* const* d_in, const int* in_sizes, int n_in,
                              void* d_out, int out_size)
{
    const float* x  = (const float*)d_in[0];
    const float* wq = (const float*)d_in[1];
    const float* bq = (const float*)d_in[2];
    const float* wk = (const float*)d_in[3];
    const float* bk = (const float*)d_in[4];
    const float* wv = (const float*)d_in[5];
    const float* bv = (const float*)d_in[6];
    const float* wo = (const float*)d_in[7];
    const float* bo = (const float*)d_in[8];
    float* out = (float*)d_out;

    cudaFuncSetAttribute(attn_mma_kernel,
                         cudaFuncAttributeMaxDynamicSharedMemorySize, ASMEM);

    rope_init_kernel<<<(T_ * D_ + 511) / 512, 512>>>();

    const int nx4 = M_ * C_ / 4;
    const int nw4 = C_ * C_ / 4;
    cvt_kernel<<<(nx4 + 255) / 256, 256>>>(x,  0, nx4);
    cvt_kernel<<<(nw4 + 255) / 256, 256>>>(wq, 1, nw4);
    cvt_kernel<<<(nw4 + 255) / 256, 256>>>(wk, 2, nw4);
    cvt_kernel<<<(nw4 + 255) / 256, 256>>>(wv, 3, nw4);
    cvt_kernel<<<(nw4 + 255) / 256, 256>>>(wo, 4, nw4);

    dim3 gqkv(C_ / 128, M_ / 128, 3);       // (8, 32, 3)
    qkv_mma_kernel<<<gqkv, 256>>>(bq, bk, bv);

    dim3 gattn(T_ / 128, B_ * H_);          // (16, 32)
    attn_mma_kernel<<<gattn, 256, ASMEM>>>();

    dim3 gout(C_ / 128, M_ / 128);          // (8, 32)
    oproj_mma_kernel<<<gout, 256>>>(bo, out);
}